// round 5
// baseline (speedup 1.0000x reference)
#include <cuda_runtime.h>
#include <math.h>

// Problem constants (fixed shapes: x is [8192, 512] fp32, output is scalar fp32)
#define N_ROWS 8192
#define DIM    512
#define KNN    5
#define EPSV   1e-8f

// GEMM tiling
#define BM 64
#define BN 64
#define BK 16
#define NTILE   (N_ROWS / BN)   // 128 column tiles
#define KCHUNKS (DIM / BK)      // 32 k-chunks
#define GRID_GRAM (N_ROWS / BM) // 128 CTAs

// Scratch (no cudaMalloc allowed -> __device__ globals)
__device__ float g_xn[N_ROWS * DIM];      // normalized rows, fp32 (16 MB)
__device__ float g_partials[GRID_GRAM];   // per-CTA partial sums of log(mean_rho+eps)

// ---------------------------------------------------------------------------
// Kernel 1: row L2-normalize. One block per row, 128 threads, float4 I/O.
// ---------------------------------------------------------------------------
__global__ void __launch_bounds__(128) normalize_kernel(const float* __restrict__ x) {
    const int row = blockIdx.x;
    const int t   = threadIdx.x;

    const float4 v = *reinterpret_cast<const float4*>(x + (size_t)row * DIM + t * 4);
    float ss = v.x * v.x + v.y * v.y + v.z * v.z + v.w * v.w;

    // warp reduce
    #pragma unroll
    for (int o = 16; o > 0; o >>= 1)
        ss += __shfl_xor_sync(0xffffffffu, ss, o);

    __shared__ float wsum[4];
    if ((t & 31) == 0) wsum[t >> 5] = ss;
    __syncthreads();
    const float tot = wsum[0] + wsum[1] + wsum[2] + wsum[3];
    const float inv = 1.0f / sqrtf(tot);

    float4 o4;
    o4.x = v.x * inv; o4.y = v.y * inv; o4.z = v.z * inv; o4.w = v.w * inv;
    *reinterpret_cast<float4*>(g_xn + (size_t)row * DIM + t * 4) = o4;
}

// ---------------------------------------------------------------------------
// Kernel 2: fused Gram + per-row top-5 (values only; dist = sqrt(2-2*dot)).
// Each CTA owns 64 rows, streams all 128 column tiles of 64.
// 256 threads laid out 16x16; each thread computes a 4x4 microtile and
// maintains per-row top-5 over the 4 columns it sees per tile. Cross-thread
// merge happens once at the end via shared memory.
// ---------------------------------------------------------------------------
__global__ void __launch_bounds__(256) gram_topk_kernel() {
    __shared__ __align__(16) float As[2][BK][BM + 4];
    __shared__ __align__(16) float Bs[2][BK][BN + 4];
    __shared__ float red[BM * 80];  // [64 rows][16 threads * 5 slots]

    const int tid = threadIdx.x;
    const int tx  = tid & 15;       // column group 0..15
    const int ty  = tid >> 4;       // row group    0..15
    const int rowBase = blockIdx.x * BM;

    // loader indexing: each thread loads 4 consecutive k for one row of A and B
    const int lr = tid >> 2;        // 0..63
    const int lk = (tid & 3) * 4;   // 0,4,8,12

    const float* aRow = g_xn + (size_t)(rowBase + lr) * DIM + lk;

    // per-thread top-5 per owned row (sorted descending)
    float tk[4][KNN];
    #pragma unroll
    for (int r = 0; r < 4; ++r)
        #pragma unroll
        for (int s = 0; s < KNN; ++s)
            tk[r][s] = -2.0f;

    #pragma unroll 1
    for (int jt = 0; jt < NTILE; ++jt) {
        const int colBase = jt * BN;
        const float* bRow = g_xn + (size_t)(colBase + lr) * DIM + lk;

        float acc[4][4];
        #pragma unroll
        for (int i = 0; i < 4; ++i)
            #pragma unroll
            for (int j = 0; j < 4; ++j)
                acc[i][j] = 0.0f;

        // prologue: stage chunk 0 into buffer 0
        int buf = 0;
        {
            const float4 ra = *reinterpret_cast<const float4*>(aRow);
            const float4 rb = *reinterpret_cast<const float4*>(bRow);
            const float* rap = reinterpret_cast<const float*>(&ra);
            const float* rbp = reinterpret_cast<const float*>(&rb);
            #pragma unroll
            for (int i = 0; i < 4; ++i) {
                As[0][lk + i][lr] = rap[i];
                Bs[0][lk + i][lr] = rbp[i];
            }
        }
        __syncthreads();

        #pragma unroll 1
        for (int kc = 0; kc < KCHUNKS; ++kc) {
            float4 na, nb;
            if (kc + 1 < KCHUNKS) {
                na = *reinterpret_cast<const float4*>(aRow + (kc + 1) * BK);
                nb = *reinterpret_cast<const float4*>(bRow + (kc + 1) * BK);
            }

            // compute on current buffer
            #pragma unroll
            for (int k = 0; k < BK; ++k) {
                const float4 a4 = *reinterpret_cast<const float4*>(&As[buf][k][ty * 4]);
                const float4 b4 = *reinterpret_cast<const float4*>(&Bs[buf][k][tx * 4]);
                const float a[4] = {a4.x, a4.y, a4.z, a4.w};
                const float b[4] = {b4.x, b4.y, b4.z, b4.w};
                #pragma unroll
                for (int i = 0; i < 4; ++i)
                    #pragma unroll
                    for (int j = 0; j < 4; ++j)
                        acc[i][j] = fmaf(a[i], b[j], acc[i][j]);
            }

            // stage next chunk into the other buffer (safe: that buffer was
            // last read in iteration kc-1, which completed before the sync at
            // the end of kc-1); one sync per iteration.
            if (kc + 1 < KCHUNKS) {
                const int nbuf = buf ^ 1;
                const float* nap = reinterpret_cast<const float*>(&na);
                const float* nbp = reinterpret_cast<const float*>(&nb);
                #pragma unroll
                for (int i = 0; i < 4; ++i) {
                    As[nbuf][lk + i][lr] = nap[i];
                    Bs[nbuf][lk + i][lr] = nbp[i];
                }
                __syncthreads();
                buf = nbuf;
            }
        }

        // epilogue: fold this 4x4 microtile into per-row top-5
        #pragma unroll
        for (int i = 0; i < 4; ++i) {
            const int grow = rowBase + ty * 4 + i;
            #pragma unroll
            for (int j = 0; j < 4; ++j) {
                const int gcol = colBase + tx * 4 + j;
                float v = (gcol == grow) ? -1.0f : acc[i][j];
                #pragma unroll
                for (int s = 0; s < KNN; ++s) {
                    if (v > tk[i][s]) { const float t = tk[i][s]; tk[i][s] = v; v = t; }
                }
            }
        }
        __syncthreads();  // protect smem buffers before next tile's prologue
    }

    // cross-thread merge: 16 threads (tx dimension) hold partial top-5 per row
    #pragma unroll
    for (int i = 0; i < 4; ++i) {
        const int r = ty * 4 + i;
        #pragma unroll
        for (int s = 0; s < KNN; ++s)
            red[r * 80 + tx * KNN + s] = tk[i][s];
    }
    __syncthreads();

    float part = 0.0f;
    if (tid < BM) {
        float t5[KNN];
        #pragma unroll
        for (int s = 0; s < KNN; ++s) t5[s] = -2.0f;
        const float* rr = &red[tid * 80];
        #pragma unroll 4
        for (int i = 0; i < 80; ++i) {
            float v = rr[i];
            #pragma unroll
            for (int s = 0; s < KNN; ++s) {
                if (v > t5[s]) { const float t = t5[s]; t5[s] = v; v = t; }
            }
        }
        float mean = 0.0f;
        #pragma unroll
        for (int s = 0; s < KNN; ++s)
            mean += sqrtf(fmaxf(2.0f - 2.0f * t5[s], 0.0f));
        mean *= (1.0f / KNN);
        part = logf(mean + EPSV);
    }
    __syncthreads();
    if (tid < BM) red[tid] = part;
    __syncthreads();

    if (tid == 0) {
        float s = 0.0f;
        #pragma unroll 8
        for (int i = 0; i < BM; ++i) s += red[i];
        g_partials[blockIdx.x] = s;
    }
}

// ---------------------------------------------------------------------------
// Kernel 3: deterministic final reduction of 128 partials -> loss.
// ---------------------------------------------------------------------------
__global__ void __launch_bounds__(128) finalize_kernel(float* __restrict__ out) {
    const int t = threadIdx.x;
    float v = g_partials[t];
    #pragma unroll
    for (int o = 16; o > 0; o >>= 1)
        v += __shfl_xor_sync(0xffffffffu, v, o);
    __shared__ float wsum[4];
    if ((t & 31) == 0) wsum[t >> 5] = v;
    __syncthreads();
    if (t == 0) {
        const float total = wsum[0] + wsum[1] + wsum[2] + wsum[3];
        out[0] = -total / (float)N_ROWS;
    }
}

// ---------------------------------------------------------------------------
extern "C" void kernel_launch(void* const* d_in, const int* in_sizes, int n_in,
                              void* d_out, int out_size) {
    (void)in_sizes; (void)n_in; (void)out_size;
    const float* x = (const float*)d_in[0];
    float* out = (float*)d_out;

    normalize_kernel<<<N_ROWS, 128>>>(x);
    gram_topk_kernel<<<GRID_GRAM, 256>>>();
    finalize_kernel<<<1, 128>>>(out);
}

// round 10
// speedup vs baseline: 9.5108x; 9.5108x over previous
#include <cuda_runtime.h>
#include <cuda_bf16.h>
#include <math.h>
#include <stdint.h>

// ---------------------------------------------------------------------------
// Problem constants
// ---------------------------------------------------------------------------
#define N_ROWS 8192
#define DIM    512
#define KNN    5
#define EPSV   1e-8f

#define GRID_GRAM       128    // 64 row stripes x 2 column halves
#define TILES_PER_CTA   32     // 128-wide column tiles per half
#define CHUNKS_PER_TILE 8      // K chunks of 64 bf16 (128 B/row)
#define TOTAL_CHUNKS    (TILES_PER_CTA * CHUNKS_PER_TILE)   // 256

// Dynamic smem: A stripe 128 KB + 4 B-slots of 16 KB
#define SM_A        0
#define SM_B        131072
#define SMEM_BYTES  (131072 + 4 * 16384)   // 196608

// ---------------------------------------------------------------------------
// Scratch (__device__ globals; no cudaMalloc allowed)
// ---------------------------------------------------------------------------
__device__ __align__(1024) __nv_bfloat16 g_xb[N_ROWS * DIM];  // normalized bf16
__device__ float g_top[2 * N_ROWS * KNN];
__device__ float g_partials[64];

// ---------------------------------------------------------------------------
// PTX helpers (all sm_80-era: valid on plain sm_103 target)
// ---------------------------------------------------------------------------
__device__ __forceinline__ uint32_t smem_u32(const void* p) {
    uint32_t a;
    asm("{ .reg .u64 t; cvta.to.shared.u64 t, %1; cvt.u32.u64 %0, t; }" : "=r"(a) : "l"(p));
    return a;
}

#define CP_ASYNC16(saddr, gptr) \
    asm volatile("cp.async.cg.shared.global [%0], [%1], 16;" :: "r"(saddr), "l"(gptr))
#define CP_COMMIT()  asm volatile("cp.async.commit_group;" ::: "memory")
#define CP_WAIT3()   asm volatile("cp.async.wait_group 3;" ::: "memory")

__device__ __forceinline__ void ldsm_x4(uint32_t& r0, uint32_t& r1, uint32_t& r2,
                                        uint32_t& r3, uint32_t addr) {
    asm volatile("ldmatrix.sync.aligned.m8n8.x4.shared.b16 {%0,%1,%2,%3}, [%4];"
                 : "=r"(r0), "=r"(r1), "=r"(r2), "=r"(r3) : "r"(addr));
}
__device__ __forceinline__ void ldsm_x2(uint32_t& r0, uint32_t& r1, uint32_t addr) {
    asm volatile("ldmatrix.sync.aligned.m8n8.x2.shared.b16 {%0,%1}, [%2];"
                 : "=r"(r0), "=r"(r1) : "r"(addr));
}
__device__ __forceinline__ void mma16816(float* c, const uint32_t* a, const uint32_t* b) {
    asm volatile("mma.sync.aligned.m16n8k16.row.col.f32.bf16.bf16.f32 "
                 "{%0,%1,%2,%3}, {%4,%5,%6,%7}, {%8,%9}, {%0,%1,%2,%3};"
                 : "+f"(c[0]), "+f"(c[1]), "+f"(c[2]), "+f"(c[3])
                 : "r"(a[0]), "r"(a[1]), "r"(a[2]), "r"(a[3]), "r"(b[0]), "r"(b[1]));
}

__device__ __forceinline__ void ins5(float t[KNN], float v, bool ok) {
    if (ok && v > t[KNN - 1]) {
        float vv = v;
        #pragma unroll
        for (int s = 0; s < KNN; ++s) {
            if (vv > t[s]) { const float tm = t[s]; t[s] = vv; vv = tm; }
        }
    }
}

// ---------------------------------------------------------------------------
// Kernel 1: row L2-normalize -> bf16
// ---------------------------------------------------------------------------
__global__ void __launch_bounds__(128) normalize_bf16_kernel(const float* __restrict__ x) {
    const int row = blockIdx.x;
    const int t   = threadIdx.x;

    const float4 v = *reinterpret_cast<const float4*>(x + (size_t)row * DIM + t * 4);
    float ss = v.x * v.x + v.y * v.y + v.z * v.z + v.w * v.w;
    #pragma unroll
    for (int o = 16; o > 0; o >>= 1) ss += __shfl_xor_sync(0xffffffffu, ss, o);

    __shared__ float wsum[4];
    if ((t & 31) == 0) wsum[t >> 5] = ss;
    __syncthreads();
    const float inv = 1.0f / sqrtf(wsum[0] + wsum[1] + wsum[2] + wsum[3]);

    __nv_bfloat162 p0 = __floats2bfloat162_rn(v.x * inv, v.y * inv);
    __nv_bfloat162 p1 = __floats2bfloat162_rn(v.z * inv, v.w * inv);
    uint2 pk;
    pk.x = *reinterpret_cast<uint32_t*>(&p0);
    pk.y = *reinterpret_cast<uint32_t*>(&p1);
    *reinterpret_cast<uint2*>(reinterpret_cast<char*>(g_xb) + (size_t)row * 1024 + t * 8) = pk;
}

// ---------------------------------------------------------------------------
// Kernel 2: bf16 HMMA Gram + fused per-row top-5
// CTA: 128 rows x 4096 cols (one half). 8 warps: warpM = wid&1 (64 rows),
// warpN = wid>>1 (32 cols). mma.m16n8k16, fp32 accum.
// ---------------------------------------------------------------------------
__global__ void __launch_bounds__(256, 1) gram_topk_mma_kernel() {
    extern __shared__ char smem[];
    const uint32_t sbase = smem_u32(smem);
    const uint32_t sA = sbase + SM_A;
    const uint32_t sB = sbase + SM_B;

    const int tid   = threadIdx.x;
    const int lane  = tid & 31;
    const int wid   = tid >> 5;
    const int warpM = wid & 1;
    const int warpN = wid >> 1;

    const int rowBase  = (blockIdx.x >> 1) * 128;
    const int half     = blockIdx.x & 1;
    const int halfBase = half * 4096;
    const char* xb = reinterpret_cast<const char*>(g_xb);

    // ---- Prologue: A stripe (128 x 512 bf16) via cp.async, XOR-swizzled ----
    #pragma unroll 8
    for (int i = 0; i < 32; ++i) {
        const int lin = tid + i * 256;          // 0..8191  (16B units)
        const int r = lin >> 6, c = lin & 63;
        const uint32_t so = sA + r * 1024 + ((c ^ (r & 7)) << 4);
        CP_ASYNC16(so, xb + (size_t)(rowBase + r) * 1024 + c * 16);
    }
    CP_COMMIT();

    // ---- Prologue: B chunks 0..2 ----
    #pragma unroll 1
    for (int pc = 0; pc < 3; ++pc) {
        const int jt = pc >> 3, cc = pc & 7, slot = pc & 3;
        const int colRow0 = halfBase + jt * 128;
        #pragma unroll
        for (int i = 0; i < 4; ++i) {
            const int lin = tid + i * 256;      // 0..1023
            const int r = lin >> 3, c = lin & 7;
            const uint32_t so = sB + slot * 16384 + r * 128 + ((c ^ (r & 7)) << 4);
            CP_ASYNC16(so, xb + (size_t)(colRow0 + r) * 1024 + cc * 128 + c * 16);
        }
        CP_COMMIT();
    }

    float acc[4][4][4];
    #pragma unroll
    for (int mt = 0; mt < 4; ++mt)
        #pragma unroll
        for (int nt = 0; nt < 4; ++nt)
            #pragma unroll
            for (int e = 0; e < 4; ++e) acc[mt][nt][e] = 0.0f;

    float t5[8][KNN];
    #pragma unroll
    for (int r = 0; r < 8; ++r)
        #pragma unroll
        for (int s = 0; s < KNN; ++s) t5[r][s] = -2.0f;

    const int swz = lane & 7;  // (row & 7) for both A and B ldmatrix rows

    // ---- Main loop: 256 flattened k-chunks, prefetch distance 3 ----
    #pragma unroll 1
    for (int gc = 0; gc < TOTAL_CHUNKS; ++gc) {
        const int pf = gc + 3;
        if (pf < TOTAL_CHUNKS) {
            const int jt = pf >> 3, cc = pf & 7, slot = pf & 3;
            const int colRow0 = halfBase + jt * 128;
            #pragma unroll
            for (int i = 0; i < 4; ++i) {
                const int lin = tid + i * 256;
                const int r = lin >> 3, c = lin & 7;
                const uint32_t so = sB + slot * 16384 + r * 128 + ((c ^ (r & 7)) << 4);
                CP_ASYNC16(so, xb + (size_t)(colRow0 + r) * 1024 + cc * 128 + c * 16);
            }
        }
        CP_COMMIT();      // empty-commit at tail keeps wait_group arithmetic exact
        CP_WAIT3();       // chunk gc resident
        __syncthreads();

        const int kc  = gc & 7;            // k-chunk within tile
        const int buf = gc & 3;
        const uint32_t sBbuf = sB + buf * 16384;

        #pragma unroll
        for (int s = 0; s < 4; ++s) {      // 4 k16 steps per 64-wide chunk
            uint32_t a[4][4];
            const int c16A = ((kc * 4 + s) << 1) + (lane >> 4);
            #pragma unroll
            for (int mt = 0; mt < 4; ++mt) {
                const int r = warpM * 64 + mt * 16 + (lane & 15);
                ldsm_x4(a[mt][0], a[mt][1], a[mt][2], a[mt][3],
                        sA + r * 1024 + ((c16A ^ swz) << 4));
            }
            uint32_t b[4][2];
            const int c16B = (s << 1) + ((lane >> 3) & 1);
            #pragma unroll
            for (int nt = 0; nt < 4; ++nt) {
                const int rn = warpN * 32 + nt * 8 + (lane & 7);
                ldsm_x2(b[nt][0], b[nt][1],
                        sBbuf + rn * 128 + ((c16B ^ swz) << 4));
            }
            #pragma unroll
            for (int mt = 0; mt < 4; ++mt)
                #pragma unroll
                for (int nt = 0; nt < 4; ++nt)
                    mma16816(acc[mt][nt], a[mt], b[nt]);
        }

        // tile finished -> fold into per-row top-5, reset accumulators
        if (kc == 7) {
            const int jt = gc >> 3;
            #pragma unroll
            for (int mt = 0; mt < 4; ++mt) {
                const int row0 = rowBase + warpM * 64 + mt * 16 + (lane >> 2);
                #pragma unroll
                for (int nt = 0; nt < 4; ++nt) {
                    const int col0 = halfBase + jt * 128 + warpN * 32 + nt * 8 + (lane & 3) * 2;
                    ins5(t5[mt * 2 + 0], acc[mt][nt][0], row0     != col0);
                    ins5(t5[mt * 2 + 0], acc[mt][nt][1], row0     != col0 + 1);
                    ins5(t5[mt * 2 + 1], acc[mt][nt][2], row0 + 8 != col0);
                    ins5(t5[mt * 2 + 1], acc[mt][nt][3], row0 + 8 != col0 + 1);
                    #pragma unroll
                    for (int e = 0; e < 4; ++e) acc[mt][nt][e] = 0.0f;
                }
            }
        }
        __syncthreads();  // protect buf before it is re-filled at gc+1's issue
    }

    // ---- Intra-CTA merge: 16 partial top-5 lists per row (reuse A smem) ----
    __syncthreads();
    float* mbuf = reinterpret_cast<float*>(smem);
    #pragma unroll
    for (int mt = 0; mt < 4; ++mt)
        #pragma unroll
        for (int rh = 0; rh < 2; ++rh) {
            const int r    = warpM * 64 + mt * 16 + rh * 8 + (lane >> 2);
            const int slot = warpN * 4 + (lane & 3);
            #pragma unroll
            for (int s = 0; s < KNN; ++s)
                mbuf[r * 80 + slot * KNN + s] = t5[mt * 2 + rh][s];
        }
    __syncthreads();

    if (tid < 128) {
        float b5[KNN];
        #pragma unroll
        for (int s = 0; s < KNN; ++s) b5[s] = -2.0f;
        const float* rr = &mbuf[tid * 80];
        #pragma unroll 4
        for (int i = 0; i < 80; ++i) {
            float v = rr[i];
            #pragma unroll
            for (int s = 0; s < KNN; ++s) {
                if (v > b5[s]) { const float tm = b5[s]; b5[s] = v; v = tm; }
            }
        }
        #pragma unroll
        for (int s = 0; s < KNN; ++s)
            g_top[((size_t)half * N_ROWS + rowBase + tid) * KNN + s] = b5[s];
    }
}

// ---------------------------------------------------------------------------
// Kernel 3: merge halves, per-row log term, block partial sums
// ---------------------------------------------------------------------------
__global__ void __launch_bounds__(128) merge_kernel() {
    const int t = threadIdx.x;
    const int row = blockIdx.x * 128 + t;

    float t5[KNN];
    #pragma unroll
    for (int s = 0; s < KNN; ++s) t5[s] = -2.0f;
    #pragma unroll
    for (int h = 0; h < 2; ++h) {
        #pragma unroll
        for (int s = 0; s < KNN; ++s) {
            float v = g_top[((size_t)h * N_ROWS + row) * KNN + s];
            #pragma unroll
            for (int q = 0; q < KNN; ++q) {
                if (v > t5[q]) { const float tm = t5[q]; t5[q] = v; v = tm; }
            }
        }
    }
    float mean = 0.0f;
    #pragma unroll
    for (int s = 0; s < KNN; ++s)
        mean += sqrtf(fmaxf(2.0f - 2.0f * t5[s], 0.0f));
    mean *= (1.0f / KNN);
    float part = logf(mean + EPSV);

    #pragma unroll
    for (int o = 16; o > 0; o >>= 1) part += __shfl_xor_sync(0xffffffffu, part, o);
    __shared__ float wsum[4];
    if ((t & 31) == 0) wsum[t >> 5] = part;
    __syncthreads();
    if (t == 0) g_partials[blockIdx.x] = wsum[0] + wsum[1] + wsum[2] + wsum[3];
}

__global__ void __launch_bounds__(64) finalize_kernel(float* __restrict__ out) {
    const int t = threadIdx.x;
    float v = g_partials[t];
    #pragma unroll
    for (int o = 16; o > 0; o >>= 1) v += __shfl_xor_sync(0xffffffffu, v, o);
    __shared__ float wsum[2];
    if ((t & 31) == 0) wsum[t >> 5] = v;
    __syncthreads();
    if (t == 0) out[0] = -(wsum[0] + wsum[1]) / (float)N_ROWS;
}

// ---------------------------------------------------------------------------
extern "C" void kernel_launch(void* const* d_in, const int* in_sizes, int n_in,
                              void* d_out, int out_size) {
    (void)in_sizes; (void)n_in; (void)out_size;
    const float* x = (const float*)d_in[0];
    float* out = (float*)d_out;

    cudaFuncSetAttribute(gram_topk_mma_kernel,
                         cudaFuncAttributeMaxDynamicSharedMemorySize, SMEM_BYTES);

    normalize_bf16_kernel<<<N_ROWS, 128>>>(x);
    gram_topk_mma_kernel<<<GRID_GRAM, 256, SMEM_BYTES>>>();
    merge_kernel<<<64, 128>>>();
    finalize_kernel<<<1, 64>>>(out);
}